// round 2
// baseline (speedup 1.0000x reference)
#include <cuda_runtime.h>
#include <cuda_bf16.h>
#include <cstdint>

// ====================== helpers (sm_80+ PTX only; no tcgen05) ======================
__device__ __forceinline__ uint32_t smem_u32(const void* p) {
    uint32_t a;
    asm("{ .reg .u64 t; cvta.to.shared.u64 t, %1; cvt.u32.u64 %0, t; }" : "=r"(a) : "l"(p));
    return a;
}

// cvt two fp32 -> packed bf16x2 (first arg -> low half)
__device__ __forceinline__ uint32_t f2bf2(float lo, float hi) {
    uint32_t r;
    asm("cvt.rn.bf16x2.f32 %0, %1, %2;" : "=r"(r) : "f"(hi), "f"(lo));
    return r;
}
__device__ __forceinline__ float bf_lowf(uint32_t p)  { return __uint_as_float(p << 16); }
__device__ __forceinline__ float bf_highf(uint32_t p) { return __uint_as_float(p & 0xFFFF0000u); }

__device__ __forceinline__ void ldsm_x4(uint32_t* d, uint32_t addr) {
    asm volatile("ldmatrix.sync.aligned.m8n8.x4.shared.b16 {%0,%1,%2,%3}, [%4];"
        : "=r"(d[0]), "=r"(d[1]), "=r"(d[2]), "=r"(d[3]) : "r"(addr));
}
__device__ __forceinline__ void ldsm_x4t(uint32_t* d, uint32_t addr) {
    asm volatile("ldmatrix.sync.aligned.m8n8.x4.trans.shared.b16 {%0,%1,%2,%3}, [%4];"
        : "=r"(d[0]), "=r"(d[1]), "=r"(d[2]), "=r"(d[3]) : "r"(addr));
}
__device__ __forceinline__ void mma_bf16(float* c, const uint32_t* a, uint32_t b0, uint32_t b1) {
    asm volatile(
        "mma.sync.aligned.m16n8k16.row.col.f32.bf16.bf16.f32 "
        "{%0,%1,%2,%3}, {%4,%5,%6,%7}, {%8,%9}, {%0,%1,%2,%3};"
        : "+f"(c[0]), "+f"(c[1]), "+f"(c[2]), "+f"(c[3])
        : "r"(a[0]), "r"(a[1]), "r"(a[2]), "r"(a[3]), "r"(b0), "r"(b1));
}

// ====================== smem layout ======================
// A_hi : 128 rows x 128 bf16, 16B-chunk XOR swizzle   = 32768 B @ 0
// A_lo : same                                          = 32768 B @ 32768
// B_hi : 128 rows(K) x 64 bf16 (W, row-major K x N)    = 16384 B @ 65536
// B_lo : same                                          = 16384 B @ 81920
// w    : 32 blocks x 16 fp32                           =  2048 B @ 98304
// bias : 64 fp32                                       =   256 B @ 100352
// H (epilogue, 128 x 68 fp32 = 34816 B) overlays A_hi after MMA.
#define SM_AHI   0u
#define SM_ALO   32768u
#define SM_BHI   65536u
#define SM_BLO   81920u
#define SM_W     98304u
#define SM_BIAS  100352u
#define SMEM_TOTAL 100608
#define SM_H     0u
#define H_STRIDE 68

__global__ void __launch_bounds__(256, 2) gcn_fused_kernel(
    const float* __restrict__ feat,
    const float* __restrict__ w,
    const float* __restrict__ weight,
    const float* __restrict__ bias,
    const float* __restrict__ alpha_p,
    float* __restrict__ out,
    int n_pool_blocks)                 // = B ; anchor half of out starts at B*64
{
    extern __shared__ unsigned char s_raw[];
    const uint32_t sb = smem_u32(s_raw);
    const int tid = threadIdx.x;
    const int wid = tid >> 5;
    const int lid = tid & 31;

    const float alpha = __ldg(alpha_p);

    // ---------- feat tile: 128 rows x 128 fp32 -> bf16 hi/lo planes ----------
    {
        const float4* fp = (const float4*)(feat + (size_t)blockIdx.x * (128 * 128));
        #pragma unroll
        for (int it = 0; it < 8; ++it) {
            int ch = tid + it * 256;                 // 16B-chunk index 0..2047
            int r  = ch >> 4;                        // row 0..127
            int cc = ch & 15;                        // chunk within row
            float4 v0 = fp[ch * 2];
            float4 v1 = fp[ch * 2 + 1];
            uint32_t h01 = f2bf2(v0.x, v0.y), h23 = f2bf2(v0.z, v0.w);
            uint32_t h45 = f2bf2(v1.x, v1.y), h67 = f2bf2(v1.z, v1.w);
            float l0 = v0.x - bf_lowf(h01),  l1 = v0.y - bf_highf(h01);
            float l2 = v0.z - bf_lowf(h23),  l3 = v0.w - bf_highf(h23);
            float l4 = v1.x - bf_lowf(h45),  l5 = v1.y - bf_highf(h45);
            float l6 = v1.z - bf_lowf(h67),  l7 = v1.w - bf_highf(h67);
            uint32_t q01 = f2bf2(l0, l1), q23 = f2bf2(l2, l3);
            uint32_t q45 = f2bf2(l4, l5), q67 = f2bf2(l6, l7);
            uint32_t off = (uint32_t)r * 256u + (uint32_t)((cc ^ (r & 7)) << 4);
            *(uint4*)(s_raw + SM_AHI + off) = make_uint4(h01, h23, h45, h67);
            *(uint4*)(s_raw + SM_ALO + off) = make_uint4(q01, q23, q45, q67);
        }
    }

    // ---------- weight: 128(K) x 64(N) fp32 -> bf16 hi/lo planes (row-major K x N) ----------
    {
        const float4* wp = (const float4*)weight;
        #pragma unroll
        for (int it = 0; it < 4; ++it) {
            int ch = tid + it * 256;                 // chunk 0..1023
            int r  = ch >> 3;                        // K row 0..127
            int cc = ch & 7;                         // chunk within 64-col row
            float4 v0 = wp[ch * 2];
            float4 v1 = wp[ch * 2 + 1];
            uint32_t h01 = f2bf2(v0.x, v0.y), h23 = f2bf2(v0.z, v0.w);
            uint32_t h45 = f2bf2(v1.x, v1.y), h67 = f2bf2(v1.z, v1.w);
            float l0 = v0.x - bf_lowf(h01),  l1 = v0.y - bf_highf(h01);
            float l2 = v0.z - bf_lowf(h23),  l3 = v0.w - bf_highf(h23);
            float l4 = v1.x - bf_lowf(h45),  l5 = v1.y - bf_highf(h45);
            float l6 = v1.z - bf_lowf(h67),  l7 = v1.w - bf_highf(h67);
            uint32_t q01 = f2bf2(l0, l1), q23 = f2bf2(l2, l3);
            uint32_t q45 = f2bf2(l4, l5), q67 = f2bf2(l6, l7);
            uint32_t off = (uint32_t)r * 128u + (uint32_t)((cc ^ (r & 7)) << 4);
            *(uint4*)(s_raw + SM_BHI + off) = make_uint4(h01, h23, h45, h67);
            *(uint4*)(s_raw + SM_BLO + off) = make_uint4(q01, q23, q45, q67);
        }
    }

    // ---------- edge weights (32 blocks x 16 fp32) + bias ----------
    {
        const uint4* wsrc = (const uint4*)(w + (size_t)blockIdx.x * 512);
        if (tid < 128) *((uint4*)(s_raw + SM_W) + tid) = wsrc[tid];
        if (tid < 16)  *((uint4*)(s_raw + SM_BIAS) + tid) = ((const uint4*)bias)[tid];
    }
    __syncthreads();

    // ---------- MMA: each warp owns 16 rows x 64 cols, K = 3 x 128 (hi*Wh, lo*Wh, hi*Wl) ----------
    float acc[8][4];
    #pragma unroll
    for (int ns = 0; ns < 8; ++ns)
        #pragma unroll
        for (int i = 0; i < 4; ++i) acc[ns][i] = 0.f;

    {
        const int r0 = wid * 16;
        // per-lane ldmatrix addressing
        const int aRow = r0 + (lid & 7) + ((lid >> 3) & 1) * 8;
        const uint32_t aRowOff = (uint32_t)aRow * 256u;
        const int aS  = aRow & 7;
        const int aC0 = lid >> 4;                    // 0/1: k-chunk select
        const int bKrel = (lid & 7) + ((lid >> 3) & 1) * 8;
        const uint32_t bRowOff = (uint32_t)bKrel * 128u;
        const int bS  = bKrel & 7;
        const int bC0 = lid >> 4;                    // 0/1: n-chunk select

        #pragma unroll
        for (int seg = 0; seg < 3; ++seg) {
            const uint32_t Ab = sb + ((seg == 1) ? SM_ALO : SM_AHI);
            const uint32_t Bb = sb + ((seg == 2) ? SM_BLO : SM_BHI);
            #pragma unroll
            for (int ks = 0; ks < 8; ++ks) {
                uint32_t a[4];
                ldsm_x4(a, Ab + aRowOff + (uint32_t)((((ks << 1) + aC0) ^ aS) << 4));
                uint32_t b[16];
                const uint32_t bkb = Bb + (uint32_t)(ks * 16 * 128) + bRowOff;
                #pragma unroll
                for (int j = 0; j < 4; ++j)
                    ldsm_x4t(b + 4 * j, bkb + (uint32_t)((((j << 1) + bC0) ^ bS) << 4));
                #pragma unroll
                for (int ns = 0; ns < 8; ++ns)
                    mma_bf16(acc[ns], a,
                             b[(ns >> 1) * 4 + (ns & 1) * 2],
                             b[(ns >> 1) * 4 + (ns & 1) * 2 + 1]);
            }
        }
    }

    __syncthreads();   // all warps done reading A planes; safe to overlay H

    // ---------- accumulators -> smem H[128][64] (stride 68) ----------
    {
        float* Hp = (float*)(s_raw + SM_H);
        const int row  = wid * 16 + (lid >> 2);
        const int colb = (lid & 3) * 2;
        #pragma unroll
        for (int ns = 0; ns < 8; ++ns) {
            int c = ns * 8 + colb;
            *(float2*)(Hp + (size_t)row * H_STRIDE + c)       = make_float2(acc[ns][0], acc[ns][1]);
            *(float2*)(Hp + (size_t)(row + 8) * H_STRIDE + c) = make_float2(acc[ns][2], acc[ns][3]);
        }
    }
    __syncthreads();

    // ---------- epilogue: 32 node-blocks, 8 threads each (8 cols/thread) ----------
    {
        const int tb = tid >> 3;                   // node-block within CTA (0..31)
        const int q  = tid & 7;
        const int c0 = q << 3;                     // columns [c0, c0+8)
        const float* Hb = (const float*)(s_raw + SM_H);
        const float* ws = (const float*)(s_raw + SM_W) + tb * 16;
        const float* bs = (const float*)(s_raw + SM_BIAS);

        float a0[8], h1[8], h2[8], h3[8], bb[8];
        const float* r0p = Hb + (size_t)(4 * tb    ) * H_STRIDE + c0;
        const float* r1p = Hb + (size_t)(4 * tb + 1) * H_STRIDE + c0;
        const float* r2p = Hb + (size_t)(4 * tb + 2) * H_STRIDE + c0;
        const float* r3p = Hb + (size_t)(4 * tb + 3) * H_STRIDE + c0;
        *(float4*)(a0) = *(const float4*)(r0p); *(float4*)(a0 + 4) = *(const float4*)(r0p + 4);
        *(float4*)(h1) = *(const float4*)(r1p); *(float4*)(h1 + 4) = *(const float4*)(r1p + 4);
        *(float4*)(h2) = *(const float4*)(r2p); *(float4*)(h2 + 4) = *(const float4*)(r2p + 4);
        *(float4*)(h3) = *(const float4*)(r3p); *(float4*)(h3 + 4) = *(const float4*)(r3p + 4);
        *(float4*)(bb) = *(const float4*)(bs + c0); *(float4*)(bb + 4) = *(const float4*)(bs + c0 + 4);

        float pool[8];
        #pragma unroll
        for (int c = 0; c < 8; ++c) pool[c] = 0.f;
        #pragma unroll
        for (int j = 0; j < 4; ++j) {
            float w1 = ws[4 + j], w2 = ws[8 + j], w3 = ws[12 + j];
            #pragma unroll
            for (int c = 0; c < 8; ++c) {
                float hv = fmaf(w1, h1[c], fmaf(w2, h2[c], w3 * h3[c])) + bb[c];
                hv = (hv >= 0.f) ? hv : alpha * hv;          // prelu
                pool[c] += hv;
            }
        }
        float pn = 0.f, an = 0.f;
        float aa[8];
        #pragma unroll
        for (int c = 0; c < 8; ++c) {
            pool[c] *= 0.25f;
            pn = fmaf(pool[c], pool[c], pn);
            float x = a0[c] + bb[c];
            x = (x >= 0.f) ? x : alpha * x;
            aa[c] = x;
            an = fmaf(x, x, an);
        }
        #pragma unroll
        for (int o = 1; o < 8; o <<= 1) {
            pn += __shfl_xor_sync(0xFFFFFFFFu, pn, o);
            an += __shfl_xor_sync(0xFFFFFFFFu, an, o);
        }
        float pinv = 1.f / fmaxf(sqrtf(pn), 1e-12f);
        float ainv = 1.f / fmaxf(sqrtf(an), 1e-12f);

        size_t gb = (size_t)blockIdx.x * 32 + tb;
        float* po = out + gb * 64 + c0;
        float* ao = out + (size_t)n_pool_blocks * 64 + gb * 64 + c0;
        *(float4*)(po)     = make_float4(pool[0]*pinv, pool[1]*pinv, pool[2]*pinv, pool[3]*pinv);
        *(float4*)(po + 4) = make_float4(pool[4]*pinv, pool[5]*pinv, pool[6]*pinv, pool[7]*pinv);
        *(float4*)(ao)     = make_float4(aa[0]*ainv, aa[1]*ainv, aa[2]*ainv, aa[3]*ainv);
        *(float4*)(ao + 4) = make_float4(aa[4]*ainv, aa[5]*ainv, aa[6]*ainv, aa[7]*ainv);
    }
}

extern "C" void kernel_launch(void* const* d_in, const int* in_sizes, int n_in,
                              void* d_out, int out_size) {
    const float* feat   = (const float*)d_in[0];
    const float* w      = (const float*)d_in[1];
    const float* weight = (const float*)d_in[2];
    const float* bias   = (const float*)d_in[3];
    const float* alpha  = (const float*)d_in[4];
    float* out = (float*)d_out;

    int n_nodes = in_sizes[0] / 128;       // N = 524288
    int n_blk   = n_nodes / 4;             // B = 131072
    int grid    = n_nodes / 128;           // 4096 CTAs (128 rows each)

    cudaFuncSetAttribute(gcn_fused_kernel,
                         cudaFuncAttributeMaxDynamicSharedMemorySize, SMEM_TOTAL);
    gcn_fused_kernel<<<grid, 256, SMEM_TOTAL>>>(feat, w, weight, bias, alpha, out, n_blk);
}